// round 10
// baseline (speedup 1.0000x reference)
#include <cuda_runtime.h>
#include <cstdint>
#include <cstddef>

#define DEV __device__ __forceinline__
#define HD __host__ __device__

static constexpr double kPI = 3.14159265358979323846;

// ---------------- constexpr math ----------------
HD constexpr double creduce(double x){
  while (x >  kPI) x -= 2.0 * kPI;
  while (x < -kPI) x += 2.0 * kPI;
  return x;
}
HD constexpr double csin(double x){
  x = creduce(x);
  double t = x, s = x, x2 = x * x;
  for (int i = 1; i < 26; ++i){ t *= -x2 / (double)((2*i) * (2*i + 1)); s += t; }
  return s;
}
HD constexpr double ccos(double x){
  x = creduce(x);
  double t = 1.0, s = 1.0, x2 = x * x;
  for (int i = 1; i < 26; ++i){ t *= -x2 / (double)((2*i - 1) * (2*i)); s += t; }
  return s;
}
HD constexpr double clog(double x){
  double r = x, k = 0.0;
  while (r > 1.25) { r *= 0.5; k += 1.0; }
  while (r < 0.75) { r *= 2.0; k -= 1.0; }
  double z = (r - 1.0) / (r + 1.0), z2 = z * z, term = z, s = z;
  for (int i = 1; i < 60; ++i){ term *= z2; s += term / (double)(2*i + 1); }
  return 2.0 * s + k * 0.69314718055994530942;
}

// ---------------- mel filterbank, 2-sparse per spectral bin ----------------
HD constexpr double hz2mel(double f){ return 1127.0 * clog(1.0 + f / 700.0); }
HD constexpr double mel_lo(){ return hz2mel(80.0); }
HD constexpr double mel_step(){ return (hz2mel(7600.0) - hz2mel(80.0)) / 81.0; }
HD constexpr double bin_mel(int k){ return hz2mel(8000.0 * (double)k / 64.0); }

struct MelEnt { int ja; int jb; float wa; float wb; };

HD constexpr MelEnt mel_ent(int k){
  MelEnt e{-1, -1, 0.0f, 0.0f};
  double u = (bin_mel(k) - mel_lo()) / mel_step();
  if (u <= 0.0 || u >= 81.0) return e;
  int i = (int)u;
  double scale = (k == 32 || k == 64) ? 2.0 : 1.0;
  double wu = ((double)(i + 1) - u) * scale;
  double wl = (u - (double)i) * scale;
  if (i - 1 >= 0 && i - 1 <= 79){ e.ja = i - 1; e.wa = (float)wu; }
  if (i <= 79){ e.jb = i; e.wb = (float)wl; }
  return e;
}
HD constexpr bool bin_used(int k){
  MelEnt e = mel_ent(k);
  return e.ja >= 0 || e.jb >= 0;
}

// Emission order = exact runtime order (identical to R7's proven order):
// idx 0: bin 32; idx 1..60: r=1..15, sub (r, 64-r, 32-r, 32+r); idx 61,62: bins 16, 48.
// Runtime: bin32 (even lane), FinalX r=1..7 (even), r=8..15 (odd), pair16 (odd) -> same sequence.
HD constexpr int emit_bin(int idx){
  if (idx == 0) return 32;
  if (idx <= 60){
    int r = (idx - 1) / 4 + 1, sub = (idx - 1) % 4;
    return sub == 0 ? r : sub == 1 ? 64 - r : sub == 2 ? 32 - r : 32 + r;
  }
  return idx == 61 ? 16 : 48;
}
HD constexpr int targ(int bin, int slot){
  MelEnt e = mel_ent(bin);
  return slot ? e.jb : e.ja;
}
HD constexpr int emit_pos(int bin){
  for (int idx = 0; idx < 63; ++idx) if (emit_bin(idx) == bin) return idx;
  return -1;
}
HD constexpr bool is_first_touch(int bin, int slot){
  int j = targ(bin, slot);
  if (j < 0) return false;
  int pos = emit_pos(bin);
  for (int idx = 0; idx < pos; ++idx){
    int b2 = emit_bin(idx);
    if (targ(b2, 0) == j || targ(b2, 1) == j) return false;
  }
  if (slot == 1 && targ(bin, 0) == j) return false;
  return true;
}
HD constexpr bool mel_used(int j){
  for (int idx = 0; idx < 63; ++idx){
    int b2 = emit_bin(idx);
    if (targ(b2, 0) == j || targ(b2, 1) == j) return true;
  }
  return false;
}
HD constexpr int bitrev6(int n){
  int r = 0;
  for (int b = 0; b < 6; ++b) r |= ((n >> b) & 1) << (5 - b);
  return r;
}

// pre-halved Hann window: 0.5 * (0.5 - 0.5*cos(2*pi*m/128))
HD constexpr float hwin(int m){
  return (float)(0.5 * (0.5 - 0.5 * ccos(2.0 * kPI * (double)m / 128.0)));
}

// ---------------- magnitude ----------------
DEV float magf(float re, float im){
  float p2 = fmaf(re, re, im * im);
  p2 = fmaxf(p2, 1e-37f);
  float m;
  asm("sqrt.approx.f32 %0, %1;" : "=f"(m) : "f"(p2));
  return m;
}

// ---------------- mel scatter -> SMEM row, compile-time offsets ----------------
template<int BIN>
DEV void scatter(float* row1, float mag){
  constexpr MelEnt e = mel_ent(BIN);
  if constexpr (e.ja >= 0){
    if constexpr (is_first_touch(BIN, 0)) row1[e.ja] = e.wa * mag;
    else row1[e.ja] = fmaf(e.wa, mag, row1[e.ja]);
  }
  if constexpr (e.jb >= 0){
    if constexpr (is_first_touch(BIN, 1)) row1[e.jb] = e.wb * mag;
    else row1[e.jb] = fmaf(e.wb, mag, row1[e.jb]);
  }
}

// zero-fill never-touched filters (static offsets)
template<int J> struct ZeroLoop {
  static DEV void run(float* row1){
    if constexpr (!mel_used(J)) row1[J] = 0.0f;
    ZeroLoop<J + 1>::run(row1);
  }
};
template<> struct ZeroLoop<80>{ static DEV void run(float*){} };

// ---------------- fused window + bit-reversed load + stage-0, per 32-pos half (R8-proven) ----
template<int BASE, int M> struct Fused0 {
  static DEV void run(float* Ar, float* Ai, const float* bp){
    constexpr int s0 = bitrev6(BASE + 2*M);
    constexpr int s1 = bitrev6(BASE + 2*M + 1);
    constexpr float w0r = hwin(2*s0), w0i = hwin(2*s0 + 1);
    constexpr float w1r = hwin(2*s1), w1i = hwin(2*s1 + 1);
    float x0r = bp[2*s0], x0i = bp[2*s0 + 1];
    float x1r = bp[2*s1], x1i = bp[2*s1 + 1];
    float tr = x1r * w1r;
    float ti = x1i * w1i;
    if constexpr (w0r == 0.0f){                   // only BASE=0, M=0
      Ar[2*M]     = tr;
      Ar[2*M + 1] = -tr;
    } else {
      Ar[2*M]     = fmaf(x0r, w0r,  tr);
      Ar[2*M + 1] = fmaf(x0r, w0r, -tr);
    }
    Ai[2*M]     = fmaf(x0i, w0i,  ti);
    Ai[2*M + 1] = fmaf(x0i, w0i, -ti);
    Fused0<BASE, M + 1>::run(Ar, Ai, bp);
  }
};
template<int BASE> struct Fused0<BASE, 16>{
  static DEV void run(float*, float*, const float*){}
};

// ---------------- stage 1 on a 32-position half (R8-proven) ----------------
template<int M> struct Stage1 {
  static DEV void run(float* Ar, float* Ai){
    constexpr int j  = M & 1;
    constexpr int i0 = ((M >> 1) << 2) + j;
    constexpr int i1 = i0 + 2;
    float br_ = Ar[i1], bi_ = Ai[i1];
    float tr, ti;
    if constexpr (j == 0){ tr = br_; ti = bi_; }
    else { tr = bi_; ti = -br_; }                 // w = -i
    float ar_ = Ar[i0], ai_ = Ai[i0];
    Ar[i0] = ar_ + tr; Ai[i0] = ai_ + ti;
    Ar[i1] = ar_ - tr; Ai[i1] = ai_ - ti;
    Stage1<M + 1>::run(Ar, Ai);
  }
};
template<> struct Stage1<16>{ static DEV void run(float*, float*){} };

// ---------------- radix-4 dragonfly (stages 2+3) on a half (R8-proven) ----------
template<int G> struct R4Loop {
  static DEV void run(float* Ar, float* Ai){
    constexpr int h  = 4;
    constexpr int j  = G & 3;
    constexpr int i0 = ((G >> 2) << 4) + j;
    constexpr double ang = kPI * (double)j / 8.0;
    constexpr float c1 = (float)ccos(2.0 * ang), s1 = (float)csin(2.0 * ang);
    constexpr float c2 = (float)ccos(ang),        s2 = (float)csin(ang);
    constexpr float c3 = (float)ccos(3.0 * ang),  s3 = (float)csin(3.0 * ang);

    float x0r = Ar[i0],       x0i = Ai[i0];
    float x1r = Ar[i0 + h],   x1i = Ai[i0 + h];
    float x2r = Ar[i0 + 2*h], x2i = Ai[i0 + 2*h];
    float x3r = Ar[i0 + 3*h], x3i = Ai[i0 + 3*h];

    float u1r, u1i, u2r, u2i, u3r, u3i;
    if constexpr (j == 0){
      u1r = x2r; u1i = x2i; u2r = x1r; u2i = x1i; u3r = x3r; u3i = x3i;
    } else {
      u1r = fmaf(c2, x2r,  s2 * x2i);
      u1i = fmaf(c2, x2i, -(s2 * x2r));
      u3r = fmaf(c3, x3r,  s3 * x3i);
      u3i = fmaf(c3, x3i, -(s3 * x3r));
      if constexpr (2*j == h){
        u2r = x1i; u2i = -x1r;
      } else {
        u2r = fmaf(c1, x1r,  s1 * x1i);
        u2i = fmaf(c1, x1i, -(s1 * x1r));
      }
    }
    float r0r = x0r + u2r, r0i = x0i + u2i;
    float r1r = x0r - u2r, r1i = x0i - u2i;
    float pr  = u1r + u3r, pi  = u1i + u3i;
    float qr  = u1r - u3r, qi  = u1i - u3i;

    Ar[i0]       = r0r + pr;  Ai[i0]       = r0i + pi;
    Ar[i0 + 2*h] = r0r - pr;  Ai[i0 + 2*h] = r0i - pi;
    Ar[i0 + h]   = r1r + qi;  Ai[i0 + h]   = r1i - qr;
    Ar[i0 + 3*h] = r1r - qi;  Ai[i0 + 3*h] = r1i + qr;
    R4Loop<G + 1>::run(Ar, Ai);
  }
};
template<> struct R4Loop<8>{ static DEV void run(float*, float*){} };

// ---------------- stage 4 on a half: pairs (j, j+16) (R8-proven) -------
template<int M> struct Stage4 {
  static DEV void run(float* Ar, float* Ai){
    constexpr int i0 = M, i1 = M + 16;
    float br_ = Ar[i1], bi_ = Ai[i1];
    float tr, ti;
    if constexpr (M == 0){ tr = br_; ti = bi_; }
    else if constexpr (M == 8){ tr = bi_; ti = -br_; }
    else {
      constexpr float c = (float)ccos(kPI * (double)M / 16.0);
      constexpr float s = (float)csin(kPI * (double)M / 16.0);
      tr = fmaf(c, br_,  s * bi_);
      ti = fmaf(c, bi_, -(s * br_));
    }
    float ar_ = Ar[i0], ai_ = Ai[i0];
    Ar[i0] = ar_ + tr; Ai[i0] = ai_ + ti;
    Ar[i1] = ar_ - tr; Ai[i1] = ai_ - ti;
    Stage4<M + 1>::run(Ar, Ai);
  }
};
template<> struct Stage4<16>{ static DEV void run(float*, float*){} };

// ---------------- real-split + magnitude + mel scatter (R7-proven math) ----------------
template<int K>
DEV void do_pair_v(float P, float Q, float R, float S, float* row1){
  float zer = P + R, zei = Q - S;
  float zor = Q + S, zoi = R - P;
  constexpr float c = (float)ccos(kPI * (double)K / 64.0);
  constexpr float s = (float)csin(kPI * (double)K / 64.0);
  float A  = fmaf(c, zor,  s * zoi);
  float Bv = fmaf(c, zoi, -(s * zor));
  scatter<K>(row1, magf(zer + A, zei + Bv));
  if constexpr (bin_used(64 - K)){
    scatter<64 - K>(row1, magf(zer - A, Bv - zei));
  }
}

// Fused stage-5 + real-split body for iteration R (R7-proven):
// butterflies (R, 32-R), pairs (K=R, K=32-R). a* = lower-half operands, b* = upper-half.
template<int R>
DEV void final_body(float ar, float ai, float br, float bi,
                    float a2r, float a2i, float b2r, float b2i, float* row1){
  constexpr float c = (float)ccos(kPI * (double)R / 32.0);
  constexpr float s = (float)csin(kPI * (double)R / 32.0);
  float tr = fmaf(c, br,  s * bi);
  float ti = fmaf(c, bi, -(s * br));
  float zRr  = ar + tr, zRi  = ai + ti;            // Z[R]
  float zRpr = ar - tr, zRpi = ai - ti;            // Z[R+32]
  float t2r = fmaf(-c, b2r,  s * b2i);
  float t2i = fmaf(-c, b2i, -(s * b2r));
  float zSr  = a2r + t2r, zSi  = a2i + t2i;        // Z[32-R]
  float zSpr = a2r - t2r, zSpi = a2i - t2i;        // Z[64-R]
  do_pair_v<R>     (zRr, zRi, zSpr, zSpi, row1);   // pair R: Z[R], Z[64-R]
  do_pair_v<32 - R>(zSr, zSi, zRpr, zRpi, row1);   // pair 32-R: Z[32-R], Z[32+R]
}

// Exchange loop: even lane (pos 0-31) runs r=1..7; odd lane (pos 32-63) runs r=8..15.
// Shuffles are uniform (full warp); bodies are parity-masked, program-ordered r=1..15.
template<int R> struct FinalX {
  static DEV void run(float* Ar, float* Ai, float* row1, int parity){
    float x1 = __shfl_xor_sync(0xFFFFFFFFu, Ar[R], 1);
    float x2 = __shfl_xor_sync(0xFFFFFFFFu, Ai[R], 1);
    float x3 = __shfl_xor_sync(0xFFFFFFFFu, Ar[32 - R], 1);
    float x4 = __shfl_xor_sync(0xFFFFFFFFu, Ai[32 - R], 1);
    if constexpr (R == 8) __syncwarp();            // order seam-filter RMW across lanes
    if constexpr (R <= 7){
      if (parity == 0)
        final_body<R>(Ar[R], Ai[R], x1, x2, Ar[32-R], Ai[32-R], x3, x4, row1);
    } else {
      if (parity == 1)
        final_body<R>(x1, x2, Ar[R], Ai[R], x3, x4, Ar[32-R], Ai[32-R], row1);
    }
    FinalX<R + 1>::run(Ar, Ai, row1, parity);
  }
};
template<> struct FinalX<16>{ static DEV void run(float*, float*, float*, int){} };

// ---------------- kernel ----------------
static constexpr int TPB = 128;       // 2 threads per frame -> 64 frames/block
static constexpr int FR  = 64;
static constexpr int NCOL = 81;       // 1 raw sample + 80 mel

__global__ void __launch_bounds__(TPB, 5)
mel_kernel(const float* __restrict__ x, float* __restrict__ out){
  __shared__ float sx[FR + 128];                  // 191 staged samples
  __shared__ __align__(16) float sout[FR * NCOL];

  const int tid = threadIdx.x;
  const int t0  = blockIdx.x * FR;
  const float* xrow = x + (size_t)blockIdx.y * 16384;

  #pragma unroll
  for (int i = tid; i < FR + 127; i += TPB){
    int t = t0 + i;
    sx[i] = (t < 16384) ? xrow[t] : 0.0f;
  }
  __syncthreads();

  const int f      = tid >> 1;                    // local frame
  const int parity = tid & 1;                     // 0: positions 0-31, 1: positions 32-63
  const float* bp  = sx + f;                      // frame base
  float* row  = sout + f * NCOL;
  float* row1 = row + 1;

  float Ar[32], Ai[32];
  if (parity == 0) Fused0<0,  0>::run(Ar, Ai, bp);
  else             Fused0<32, 0>::run(Ar, Ai, bp);
  Stage1<0>::run(Ar, Ai);                         // uniform: BASE-independent
  R4Loop<0>::run(Ar, Ai);
  Stage4<0>::run(Ar, Ai);

  // bin 32: Z[32] = pos0 - pos32 (w = 1); even lane computes (partner pos32 via shfl)
  float o1 = __shfl_xor_sync(0xFFFFFFFFu, Ar[0], 1);
  float o2 = __shfl_xor_sync(0xFFFFFFFFu, Ai[0], 1);
  if (parity == 0){
    row[0] = sx[f];                               // raw passthrough
    ZeroLoop<0>::run(row1);                       // untouched filters -> 0
    scatter<32>(row1, magf(Ar[0] - o1, Ai[0] - o2));
  }

  FinalX<1>::run(Ar, Ai, row1, parity);           // r=1..7 even lanes, r=8..15 odd lanes

  // pair 16 (Z[16], Z[48]): butterfly w = -i; odd lane computes (pos16 via shfl)
  float p1 = __shfl_xor_sync(0xFFFFFFFFu, Ar[16], 1);
  float p2 = __shfl_xor_sync(0xFFFFFFFFu, Ai[16], 1);
  if (parity == 1){
    do_pair_v<16>(p1 + Ai[16], p2 - Ar[16], p1 - Ai[16], p2 + Ar[16], row1);
  }
  __syncthreads();

  // coalesced float4 copy: 64*81 = 5184 floats = 1296 float4 = 10*128 + 16
  float4* g4 = (float4*)(out + ((size_t)blockIdx.y * 16384 + (size_t)t0) * NCOL);
  const float4* s4 = (const float4*)sout;
  #pragma unroll
  for (int r = 0; r < 10; ++r) g4[tid + TPB * r] = s4[tid + TPB * r];
  if (tid < 16) g4[1280 + tid] = s4[1280 + tid];
}

extern "C" void kernel_launch(void* const* d_in, const int* in_sizes, int n_in,
                              void* d_out, int out_size){
  (void)in_sizes; (void)n_in; (void)out_size;
  const float* x = (const float*)d_in[0];
  float* out = (float*)d_out;
  dim3 grid(16384 / FR, 16);
  mel_kernel<<<grid, TPB>>>(x, out);
}

// round 11
// speedup vs baseline: 1.0064x; 1.0064x over previous
#include <cuda_runtime.h>
#include <cstdint>
#include <cstddef>

#define DEV __device__ __forceinline__
#define HD __host__ __device__

static constexpr double kPI = 3.14159265358979323846;

// ---------------- constexpr math ----------------
HD constexpr double creduce(double x){
  while (x >  kPI) x -= 2.0 * kPI;
  while (x < -kPI) x += 2.0 * kPI;
  return x;
}
HD constexpr double csin(double x){
  x = creduce(x);
  double t = x, s = x, x2 = x * x;
  for (int i = 1; i < 26; ++i){ t *= -x2 / (double)((2*i) * (2*i + 1)); s += t; }
  return s;
}
HD constexpr double ccos(double x){
  x = creduce(x);
  double t = 1.0, s = 1.0, x2 = x * x;
  for (int i = 1; i < 26; ++i){ t *= -x2 / (double)((2*i - 1) * (2*i)); s += t; }
  return s;
}
HD constexpr double clog(double x){
  double r = x, k = 0.0;
  while (r > 1.25) { r *= 0.5; k += 1.0; }
  while (r < 0.75) { r *= 2.0; k -= 1.0; }
  double z = (r - 1.0) / (r + 1.0), z2 = z * z, term = z, s = z;
  for (int i = 1; i < 60; ++i){ term *= z2; s += term / (double)(2*i + 1); }
  return 2.0 * s + k * 0.69314718055994530942;
}

// ---------------- mel filterbank, 2-sparse per spectral bin ----------------
HD constexpr double hz2mel(double f){ return 1127.0 * clog(1.0 + f / 700.0); }
HD constexpr double mel_lo(){ return hz2mel(80.0); }
HD constexpr double mel_step(){ return (hz2mel(7600.0) - hz2mel(80.0)) / 81.0; }
HD constexpr double bin_mel(int k){ return hz2mel(8000.0 * (double)k / 64.0); }

struct MelEnt { int ja; int jb; float wa; float wb; };

HD constexpr MelEnt mel_ent(int k){
  MelEnt e{-1, -1, 0.0f, 0.0f};
  double u = (bin_mel(k) - mel_lo()) / mel_step();
  if (u <= 0.0 || u >= 81.0) return e;
  int i = (int)u;
  double scale = (k == 32 || k == 64) ? 2.0 : 1.0;
  double wu = ((double)(i + 1) - u) * scale;
  double wl = (u - (double)i) * scale;
  if (i - 1 >= 0 && i - 1 <= 79){ e.ja = i - 1; e.wa = (float)wu; }
  if (i <= 79){ e.jb = i; e.wb = (float)wl; }
  return e;
}
HD constexpr bool bin_used(int k){
  MelEnt e = mel_ent(k);
  return e.ja >= 0 || e.jb >= 0;
}

// Emission order = exact runtime order (identical to R7's proven order):
// idx 0: bin 32; idx 1..60: r=1..15, sub (r, 64-r, 32-r, 32+r); idx 61,62: bins 16, 48.
// Runtime: bin32 (even lane), FinalX r=1..7 (even), r=8..15 (odd), pair16 (odd) -> same sequence.
HD constexpr int emit_bin(int idx){
  if (idx == 0) return 32;
  if (idx <= 60){
    int r = (idx - 1) / 4 + 1, sub = (idx - 1) % 4;
    return sub == 0 ? r : sub == 1 ? 64 - r : sub == 2 ? 32 - r : 32 + r;
  }
  return idx == 61 ? 16 : 48;
}
HD constexpr int targ(int bin, int slot){
  MelEnt e = mel_ent(bin);
  return slot ? e.jb : e.ja;
}
HD constexpr int emit_pos(int bin){
  for (int idx = 0; idx < 63; ++idx) if (emit_bin(idx) == bin) return idx;
  return -1;
}
HD constexpr bool is_first_touch(int bin, int slot){
  int j = targ(bin, slot);
  if (j < 0) return false;
  int pos = emit_pos(bin);
  for (int idx = 0; idx < pos; ++idx){
    int b2 = emit_bin(idx);
    if (targ(b2, 0) == j || targ(b2, 1) == j) return false;
  }
  if (slot == 1 && targ(bin, 0) == j) return false;
  return true;
}
HD constexpr bool mel_used(int j){
  for (int idx = 0; idx < 63; ++idx){
    int b2 = emit_bin(idx);
    if (targ(b2, 0) == j || targ(b2, 1) == j) return true;
  }
  return false;
}
HD constexpr int bitrev6(int n){
  int r = 0;
  for (int b = 0; b < 6; ++b) r |= ((n >> b) & 1) << (5 - b);
  return r;
}

// pre-halved Hann window: 0.5 * (0.5 - 0.5*cos(2*pi*m/128))
HD constexpr float hwin(int m){
  return (float)(0.5 * (0.5 - 0.5 * ccos(2.0 * kPI * (double)m / 128.0)));
}

// ---------------- magnitude ----------------
DEV float magf(float re, float im){
  float p2 = fmaf(re, re, im * im);
  p2 = fmaxf(p2, 1e-37f);
  float m;
  asm("sqrt.approx.f32 %0, %1;" : "=f"(m) : "f"(p2));
  return m;
}

// ---------------- mel scatter -> SMEM row, compile-time offsets ----------------
template<int BIN>
DEV void scatter(float* row1, float mag){
  constexpr MelEnt e = mel_ent(BIN);
  if constexpr (e.ja >= 0){
    if constexpr (is_first_touch(BIN, 0)) row1[e.ja] = e.wa * mag;
    else row1[e.ja] = fmaf(e.wa, mag, row1[e.ja]);
  }
  if constexpr (e.jb >= 0){
    if constexpr (is_first_touch(BIN, 1)) row1[e.jb] = e.wb * mag;
    else row1[e.jb] = fmaf(e.wb, mag, row1[e.jb]);
  }
}

// zero-fill never-touched filters (static offsets)
template<int J> struct ZeroLoop {
  static DEV void run(float* row1){
    if constexpr (!mel_used(J)) row1[J] = 0.0f;
    ZeroLoop<J + 1>::run(row1);
  }
};
template<> struct ZeroLoop<80>{ static DEV void run(float*){} };

// ---------------- fused window + bit-reversed load + stage-0, per 32-pos half (R8-proven) ----
template<int BASE, int M> struct Fused0 {
  static DEV void run(float* Ar, float* Ai, const float* bp){
    constexpr int s0 = bitrev6(BASE + 2*M);
    constexpr int s1 = bitrev6(BASE + 2*M + 1);
    constexpr float w0r = hwin(2*s0), w0i = hwin(2*s0 + 1);
    constexpr float w1r = hwin(2*s1), w1i = hwin(2*s1 + 1);
    float x0r = bp[2*s0], x0i = bp[2*s0 + 1];
    float x1r = bp[2*s1], x1i = bp[2*s1 + 1];
    float tr = x1r * w1r;
    float ti = x1i * w1i;
    if constexpr (w0r == 0.0f){                   // only BASE=0, M=0
      Ar[2*M]     = tr;
      Ar[2*M + 1] = -tr;
    } else {
      Ar[2*M]     = fmaf(x0r, w0r,  tr);
      Ar[2*M + 1] = fmaf(x0r, w0r, -tr);
    }
    Ai[2*M]     = fmaf(x0i, w0i,  ti);
    Ai[2*M + 1] = fmaf(x0i, w0i, -ti);
    Fused0<BASE, M + 1>::run(Ar, Ai, bp);
  }
};
template<int BASE> struct Fused0<BASE, 16>{
  static DEV void run(float*, float*, const float*){}
};

// ---------------- stage 1 on a 32-position half (R8-proven) ----------------
template<int M> struct Stage1 {
  static DEV void run(float* Ar, float* Ai){
    constexpr int j  = M & 1;
    constexpr int i0 = ((M >> 1) << 2) + j;
    constexpr int i1 = i0 + 2;
    float br_ = Ar[i1], bi_ = Ai[i1];
    float tr, ti;
    if constexpr (j == 0){ tr = br_; ti = bi_; }
    else { tr = bi_; ti = -br_; }                 // w = -i
    float ar_ = Ar[i0], ai_ = Ai[i0];
    Ar[i0] = ar_ + tr; Ai[i0] = ai_ + ti;
    Ar[i1] = ar_ - tr; Ai[i1] = ai_ - ti;
    Stage1<M + 1>::run(Ar, Ai);
  }
};
template<> struct Stage1<16>{ static DEV void run(float*, float*){} };

// ---------------- radix-4 dragonfly (stages 2+3) on a half (R8-proven) ----------
template<int G> struct R4Loop {
  static DEV void run(float* Ar, float* Ai){
    constexpr int h  = 4;
    constexpr int j  = G & 3;
    constexpr int i0 = ((G >> 2) << 4) + j;
    constexpr double ang = kPI * (double)j / 8.0;
    constexpr float c1 = (float)ccos(2.0 * ang), s1 = (float)csin(2.0 * ang);
    constexpr float c2 = (float)ccos(ang),        s2 = (float)csin(ang);
    constexpr float c3 = (float)ccos(3.0 * ang),  s3 = (float)csin(3.0 * ang);

    float x0r = Ar[i0],       x0i = Ai[i0];
    float x1r = Ar[i0 + h],   x1i = Ai[i0 + h];
    float x2r = Ar[i0 + 2*h], x2i = Ai[i0 + 2*h];
    float x3r = Ar[i0 + 3*h], x3i = Ai[i0 + 3*h];

    float u1r, u1i, u2r, u2i, u3r, u3i;
    if constexpr (j == 0){
      u1r = x2r; u1i = x2i; u2r = x1r; u2i = x1i; u3r = x3r; u3i = x3i;
    } else {
      u1r = fmaf(c2, x2r,  s2 * x2i);
      u1i = fmaf(c2, x2i, -(s2 * x2r));
      u3r = fmaf(c3, x3r,  s3 * x3i);
      u3i = fmaf(c3, x3i, -(s3 * x3r));
      if constexpr (2*j == h){
        u2r = x1i; u2i = -x1r;
      } else {
        u2r = fmaf(c1, x1r,  s1 * x1i);
        u2i = fmaf(c1, x1i, -(s1 * x1r));
      }
    }
    float r0r = x0r + u2r, r0i = x0i + u2i;
    float r1r = x0r - u2r, r1i = x0i - u2i;
    float pr  = u1r + u3r, pi  = u1i + u3i;
    float qr  = u1r - u3r, qi  = u1i - u3i;

    Ar[i0]       = r0r + pr;  Ai[i0]       = r0i + pi;
    Ar[i0 + 2*h] = r0r - pr;  Ai[i0 + 2*h] = r0i - pi;
    Ar[i0 + h]   = r1r + qi;  Ai[i0 + h]   = r1i - qr;
    Ar[i0 + 3*h] = r1r - qi;  Ai[i0 + 3*h] = r1i + qr;
    R4Loop<G + 1>::run(Ar, Ai);
  }
};
template<> struct R4Loop<8>{ static DEV void run(float*, float*){} };

// ---------------- stage 4 on a half: pairs (j, j+16) (R8-proven) -------
template<int M> struct Stage4 {
  static DEV void run(float* Ar, float* Ai){
    constexpr int i0 = M, i1 = M + 16;
    float br_ = Ar[i1], bi_ = Ai[i1];
    float tr, ti;
    if constexpr (M == 0){ tr = br_; ti = bi_; }
    else if constexpr (M == 8){ tr = bi_; ti = -br_; }
    else {
      constexpr float c = (float)ccos(kPI * (double)M / 16.0);
      constexpr float s = (float)csin(kPI * (double)M / 16.0);
      tr = fmaf(c, br_,  s * bi_);
      ti = fmaf(c, bi_, -(s * br_));
    }
    float ar_ = Ar[i0], ai_ = Ai[i0];
    Ar[i0] = ar_ + tr; Ai[i0] = ai_ + ti;
    Ar[i1] = ar_ - tr; Ai[i1] = ai_ - ti;
    Stage4<M + 1>::run(Ar, Ai);
  }
};
template<> struct Stage4<16>{ static DEV void run(float*, float*){} };

// ---------------- real-split + magnitude + mel scatter (R7-proven math) ----------------
template<int K>
DEV void do_pair_v(float P, float Q, float R, float S, float* row1){
  float zer = P + R, zei = Q - S;
  float zor = Q + S, zoi = R - P;
  constexpr float c = (float)ccos(kPI * (double)K / 64.0);
  constexpr float s = (float)csin(kPI * (double)K / 64.0);
  float A  = fmaf(c, zor,  s * zoi);
  float Bv = fmaf(c, zoi, -(s * zor));
  scatter<K>(row1, magf(zer + A, zei + Bv));
  if constexpr (bin_used(64 - K)){
    scatter<64 - K>(row1, magf(zer - A, Bv - zei));
  }
}

// Fused stage-5 + real-split body for iteration R (R7-proven):
// butterflies (R, 32-R), pairs (K=R, K=32-R). a* = lower-half operands, b* = upper-half.
template<int R>
DEV void final_body(float ar, float ai, float br, float bi,
                    float a2r, float a2i, float b2r, float b2i, float* row1){
  constexpr float c = (float)ccos(kPI * (double)R / 32.0);
  constexpr float s = (float)csin(kPI * (double)R / 32.0);
  float tr = fmaf(c, br,  s * bi);
  float ti = fmaf(c, bi, -(s * br));
  float zRr  = ar + tr, zRi  = ai + ti;            // Z[R]
  float zRpr = ar - tr, zRpi = ai - ti;            // Z[R+32]
  float t2r = fmaf(-c, b2r,  s * b2i);
  float t2i = fmaf(-c, b2i, -(s * b2r));
  float zSr  = a2r + t2r, zSi  = a2i + t2i;        // Z[32-R]
  float zSpr = a2r - t2r, zSpi = a2i - t2i;        // Z[64-R]
  do_pair_v<R>     (zRr, zRi, zSpr, zSpi, row1);   // pair R: Z[R], Z[64-R]
  do_pair_v<32 - R>(zSr, zSi, zRpr, zRpi, row1);   // pair 32-R: Z[32-R], Z[32+R]
}

// Exchange loop: even lane (pos 0-31) runs r=1..7; odd lane (pos 32-63) runs r=8..15.
// Shuffles are uniform (full warp); bodies are parity-masked, program-ordered r=1..15.
template<int R> struct FinalX {
  static DEV void run(float* Ar, float* Ai, float* row1, int parity){
    float x1 = __shfl_xor_sync(0xFFFFFFFFu, Ar[R], 1);
    float x2 = __shfl_xor_sync(0xFFFFFFFFu, Ai[R], 1);
    float x3 = __shfl_xor_sync(0xFFFFFFFFu, Ar[32 - R], 1);
    float x4 = __shfl_xor_sync(0xFFFFFFFFu, Ai[32 - R], 1);
    if constexpr (R == 8) __syncwarp();            // order seam-filter RMW across lanes
    if constexpr (R <= 7){
      if (parity == 0)
        final_body<R>(Ar[R], Ai[R], x1, x2, Ar[32-R], Ai[32-R], x3, x4, row1);
    } else {
      if (parity == 1)
        final_body<R>(x1, x2, Ar[R], Ai[R], x3, x4, Ar[32-R], Ai[32-R], row1);
    }
    FinalX<R + 1>::run(Ar, Ai, row1, parity);
  }
};
template<> struct FinalX<16>{ static DEV void run(float*, float*, float*, int){} };

// ---------------- kernel ----------------
static constexpr int TPB = 128;       // 2 threads per frame -> 64 frames/block
static constexpr int FR  = 64;
static constexpr int NCOL = 81;       // 1 raw sample + 80 mel

__global__ void __launch_bounds__(TPB, 5)
mel_kernel(const float* __restrict__ x, float* __restrict__ out){
  __shared__ float sx[FR + 128];                  // 191 staged samples
  __shared__ __align__(16) float sout[FR * NCOL];

  const int tid = threadIdx.x;
  const int t0  = blockIdx.x * FR;
  const float* xrow = x + (size_t)blockIdx.y * 16384;

  #pragma unroll
  for (int i = tid; i < FR + 127; i += TPB){
    int t = t0 + i;
    sx[i] = (t < 16384) ? xrow[t] : 0.0f;
  }
  __syncthreads();

  const int f      = tid >> 1;                    // local frame
  const int parity = tid & 1;                     // 0: positions 0-31, 1: positions 32-63
  const float* bp  = sx + f;                      // frame base
  float* row  = sout + f * NCOL;
  float* row1 = row + 1;

  float Ar[32], Ai[32];
  if (parity == 0) Fused0<0,  0>::run(Ar, Ai, bp);
  else             Fused0<32, 0>::run(Ar, Ai, bp);
  Stage1<0>::run(Ar, Ai);                         // uniform: BASE-independent
  R4Loop<0>::run(Ar, Ai);
  Stage4<0>::run(Ar, Ai);

  // bin 32: Z[32] = pos0 - pos32 (w = 1); even lane computes (partner pos32 via shfl)
  float o1 = __shfl_xor_sync(0xFFFFFFFFu, Ar[0], 1);
  float o2 = __shfl_xor_sync(0xFFFFFFFFu, Ai[0], 1);
  if (parity == 0){
    row[0] = sx[f];                               // raw passthrough
    ZeroLoop<0>::run(row1);                       // untouched filters -> 0
    scatter<32>(row1, magf(Ar[0] - o1, Ai[0] - o2));
  }

  FinalX<1>::run(Ar, Ai, row1, parity);           // r=1..7 even lanes, r=8..15 odd lanes

  // pair 16 (Z[16], Z[48]): butterfly w = -i; odd lane computes (pos16 via shfl)
  float p1 = __shfl_xor_sync(0xFFFFFFFFu, Ar[16], 1);
  float p2 = __shfl_xor_sync(0xFFFFFFFFu, Ai[16], 1);
  if (parity == 1){
    do_pair_v<16>(p1 + Ai[16], p2 - Ar[16], p1 - Ai[16], p2 + Ar[16], row1);
  }
  __syncthreads();

  // coalesced float4 copy: 64*81 = 5184 floats = 1296 float4 = 10*128 + 16
  float4* g4 = (float4*)(out + ((size_t)blockIdx.y * 16384 + (size_t)t0) * NCOL);
  const float4* s4 = (const float4*)sout;
  #pragma unroll
  for (int r = 0; r < 10; ++r) g4[tid + TPB * r] = s4[tid + TPB * r];
  if (tid < 16) g4[1280 + tid] = s4[1280 + tid];
}

extern "C" void kernel_launch(void* const* d_in, const int* in_sizes, int n_in,
                              void* d_out, int out_size){
  (void)in_sizes; (void)n_in; (void)out_size;
  const float* x = (const float*)d_in[0];
  float* out = (float*)d_out;
  dim3 grid(16384 / FR, 16);
  mel_kernel<<<grid, TPB>>>(x, out);
}

// round 12
// speedup vs baseline: 1.6812x; 1.6706x over previous
#include <cuda_runtime.h>
#include <cstdint>
#include <cstddef>

#define DEV __device__ __forceinline__
#define HD __host__ __device__

static constexpr double kPI = 3.14159265358979323846;

// ---------------- constexpr math (compile-time tables) ----------------
HD constexpr double creduce(double x){
  while (x >  kPI) x -= 2.0 * kPI;
  while (x < -kPI) x += 2.0 * kPI;
  return x;
}
HD constexpr double csin(double x){
  x = creduce(x);
  double t = x, s = x, x2 = x * x;
  for (int i = 1; i < 26; ++i){ t *= -x2 / (double)((2*i) * (2*i + 1)); s += t; }
  return s;
}
HD constexpr double ccos(double x){
  x = creduce(x);
  double t = 1.0, s = 1.0, x2 = x * x;
  for (int i = 1; i < 26; ++i){ t *= -x2 / (double)((2*i - 1) * (2*i)); s += t; }
  return s;
}
HD constexpr double clog(double x){
  double r = x, k = 0.0;
  while (r > 1.25) { r *= 0.5; k += 1.0; }
  while (r < 0.75) { r *= 2.0; k -= 1.0; }
  double z = (r - 1.0) / (r + 1.0), z2 = z * z, term = z, s = z;
  for (int i = 1; i < 60; ++i){ term *= z2; s += term / (double)(2*i + 1); }
  return 2.0 * s + k * 0.69314718055994530942;
}

// ---------------- mel filterbank, 2-sparse per spectral bin ----------------
HD constexpr double hz2mel(double f){ return 1127.0 * clog(1.0 + f / 700.0); }
HD constexpr double mel_lo(){ return hz2mel(80.0); }
HD constexpr double mel_step(){ return (hz2mel(7600.0) - hz2mel(80.0)) / 81.0; }
HD constexpr double bin_mel(int k){ return hz2mel(8000.0 * (double)k / 64.0); }

struct MelEnt { int ja; int jb; float wa; float wb; };

HD constexpr MelEnt mel_ent(int k){
  MelEnt e{-1, -1, 0.0f, 0.0f};
  double u = (bin_mel(k) - mel_lo()) / mel_step();
  if (u <= 0.0 || u >= 81.0) return e;
  int i = (int)u;
  double scale = (k == 32 || k == 64) ? 2.0 : 1.0;
  double wu = ((double)(i + 1) - u) * scale;
  double wl = (u - (double)i) * scale;
  if (i - 1 >= 0 && i - 1 <= 79){ e.ja = i - 1; e.wa = (float)wu; }
  if (i <= 79){ e.jb = i; e.wb = (float)wl; }
  return e;
}
HD constexpr bool bin_used(int k){
  MelEnt e = mel_ent(k);
  return e.ja >= 0 || e.jb >= 0;
}

// Emission order = exact runtime order of the fused final loop (R7-proven):
// idx 0: bin 32; idx 1..60: r=1..15, sub order (r, 64-r, 32-r, 32+r); idx 61,62: bins 16, 48.
HD constexpr int emit_bin(int idx){
  if (idx == 0) return 32;
  if (idx <= 60){
    int r = (idx - 1) / 4 + 1, sub = (idx - 1) % 4;
    return sub == 0 ? r : sub == 1 ? 64 - r : sub == 2 ? 32 - r : 32 + r;
  }
  return idx == 61 ? 16 : 48;
}
HD constexpr int targ(int bin, int slot){
  MelEnt e = mel_ent(bin);
  return slot ? e.jb : e.ja;
}
HD constexpr int emit_pos(int bin){
  for (int idx = 0; idx < 63; ++idx) if (emit_bin(idx) == bin) return idx;
  return -1;
}
HD constexpr bool is_first_touch(int bin, int slot){
  int j = targ(bin, slot);
  if (j < 0) return false;
  int pos = emit_pos(bin);
  for (int idx = 0; idx < pos; ++idx){
    int b2 = emit_bin(idx);
    if (targ(b2, 0) == j || targ(b2, 1) == j) return false;
  }
  if (slot == 1 && targ(bin, 0) == j) return false;
  return true;
}
HD constexpr bool mel_used(int j){
  for (int idx = 0; idx < 63; ++idx){
    int b2 = emit_bin(idx);
    if (targ(b2, 0) == j || targ(b2, 1) == j) return true;
  }
  return false;
}
HD constexpr int bitrev6(int n){
  int r = 0;
  for (int b = 0; b < 6; ++b) r |= ((n >> b) & 1) << (5 - b);
  return r;
}

// pre-halved Hann window: 0.5 * (0.5 - 0.5*cos(2*pi*m/128))
HD constexpr float hwin(int m){
  return (float)(0.5 * (0.5 - 0.5 * ccos(2.0 * kPI * (double)m / 128.0)));
}

// ---------------- magnitude: MUFU.SQRT (p2 >= 0 always; sqrt.approx(0/denorm) = 0) ----
DEV float magf(float re, float im){
  float p2 = fmaf(re, re, im * im);
  float m;
  asm("sqrt.approx.f32 %0, %1;" : "=f"(m) : "f"(p2));
  return m;
}

// ---------------- mel scatter (static register indices, proven) ----------------
template<int BIN>
DEV void scatter(float* mel, float mag){
  constexpr MelEnt e = mel_ent(BIN);
  if constexpr (e.ja >= 0){
    if constexpr (is_first_touch(BIN, 0)) mel[e.ja] = e.wa * mag;
    else mel[e.ja] = fmaf(e.wa, mag, mel[e.ja]);
  }
  if constexpr (e.jb >= 0){
    if constexpr (is_first_touch(BIN, 1)) mel[e.jb] = e.wb * mag;
    else mel[e.jb] = fmaf(e.wb, mag, mel[e.jb]);
  }
}

// ---------------- fused window + bit-reversed load + stage-0, paired LDS.64 ----------
// bp2[s] aliases (x[t0+tid+2s], x[t0+tid+2s+1]) for this thread (alignment via sxe/sxo).
template<int M> struct Fused0 {
  static DEV void run(float* Ar, float* Ai, const float2* bp2){
    constexpr int s0 = bitrev6(2*M);
    constexpr int s1 = bitrev6(2*M + 1);          // = s0 + 32
    constexpr float w0r = hwin(2*s0), w0i = hwin(2*s0 + 1);
    constexpr float w1r = hwin(2*s1), w1i = hwin(2*s1 + 1);
    float2 a = bp2[s0];
    float2 b = bp2[s1];
    float tr = b.x * w1r;
    float ti = b.y * w1i;
    if constexpr (w0r == 0.0f){                   // only s0 == 0 (window zero at m=0)
      Ar[2*M]     = tr;
      Ar[2*M + 1] = -tr;
    } else {
      Ar[2*M]     = fmaf(a.x, w0r,  tr);
      Ar[2*M + 1] = fmaf(a.x, w0r, -tr);
    }
    Ai[2*M]     = fmaf(a.y, w0i,  ti);
    Ai[2*M + 1] = fmaf(a.y, w0i, -ti);
    Fused0<M + 1>::run(Ar, Ai, bp2);
  }
};
template<> struct Fused0<32>{ static DEV void run(float*, float*, const float2*){} };

// ---------------- radix-2 stage 1 (all twiddles trivial: 1 and -i) ----------------
template<int M> struct Stage1 {
  static DEV void run(float* Ar, float* Ai){
    constexpr int j  = M & 1;
    constexpr int i0 = ((M >> 1) << 2) + j;
    constexpr int i1 = i0 + 2;
    float br_ = Ar[i1], bi_ = Ai[i1];
    float tr, ti;
    if constexpr (j == 0){ tr = br_; ti = bi_; }
    else { tr = bi_; ti = -br_; }                 // w = -i
    float ar_ = Ar[i0], ai_ = Ai[i0];
    Ar[i0] = ar_ + tr; Ai[i0] = ai_ + ti;
    Ar[i1] = ar_ - tr; Ai[i1] = ai_ - ti;
    Stage1<M + 1>::run(Ar, Ai);
  }
};
template<> struct Stage1<32>{ static DEV void run(float*, float*){} };

// ---------------- radix-4 dragonfly: fuses radix-2 stages 2 and 3 ----------------
template<int S, int G> struct R4Loop {
  static DEV void run(float* Ar, float* Ai){
    constexpr int h  = 1 << S;
    constexpr int j  = G & (h - 1);
    constexpr int i0 = ((G >> S) << (S + 2)) + j;
    constexpr double ang = kPI * (double)j / (double)(2 * h);
    constexpr float c1 = (float)ccos(2.0 * ang), s1 = (float)csin(2.0 * ang);
    constexpr float c2 = (float)ccos(ang),        s2 = (float)csin(ang);
    constexpr float c3 = (float)ccos(3.0 * ang),  s3 = (float)csin(3.0 * ang);

    float x0r = Ar[i0],       x0i = Ai[i0];
    float x1r = Ar[i0 + h],   x1i = Ai[i0 + h];
    float x2r = Ar[i0 + 2*h], x2i = Ai[i0 + 2*h];
    float x3r = Ar[i0 + 3*h], x3i = Ai[i0 + 3*h];

    float u1r, u1i, u2r, u2i, u3r, u3i;
    if constexpr (j == 0){
      u1r = x2r; u1i = x2i; u2r = x1r; u2i = x1i; u3r = x3r; u3i = x3i;
    } else {
      u1r = fmaf(c2, x2r,  s2 * x2i);
      u1i = fmaf(c2, x2i, -(s2 * x2r));
      u3r = fmaf(c3, x3r,  s3 * x3i);
      u3i = fmaf(c3, x3i, -(s3 * x3r));
      if constexpr (2*j == h){
        u2r = x1i; u2i = -x1r;
      } else {
        u2r = fmaf(c1, x1r,  s1 * x1i);
        u2i = fmaf(c1, x1i, -(s1 * x1r));
      }
    }
    float r0r = x0r + u2r, r0i = x0i + u2i;
    float r1r = x0r - u2r, r1i = x0i - u2i;
    float pr  = u1r + u3r, pi  = u1i + u3i;
    float qr  = u1r - u3r, qi  = u1i - u3i;

    Ar[i0]       = r0r + pr;  Ai[i0]       = r0i + pi;
    Ar[i0 + 2*h] = r0r - pr;  Ai[i0 + 2*h] = r0i - pi;
    Ar[i0 + h]   = r1r + qi;  Ai[i0 + h]   = r1i - qr;
    Ar[i0 + 3*h] = r1r - qi;  Ai[i0 + 3*h] = r1i + qr;
    R4Loop<S, G + 1>::run(Ar, Ai);
  }
};
template<int S> struct R4Loop<S, 16>{ static DEV void run(float*, float*){} };

// ---------------- radix-2 stage 4 (h = 16) ----------------
template<int M> struct Stage4 {
  static DEV void run(float* Ar, float* Ai){
    constexpr int j  = M & 15;
    constexpr int i0 = ((M >> 4) << 5) + j;
    constexpr int i1 = i0 + 16;
    float br_ = Ar[i1], bi_ = Ai[i1];
    float tr, ti;
    if constexpr (j == 0){ tr = br_; ti = bi_; }
    else if constexpr (j == 8){ tr = bi_; ti = -br_; }
    else {
      constexpr float c = (float)ccos(kPI * (double)j / 16.0);
      constexpr float s = (float)csin(kPI * (double)j / 16.0);
      tr = fmaf(c, br_,  s * bi_);
      ti = fmaf(c, bi_, -(s * br_));
    }
    float ar_ = Ar[i0], ai_ = Ai[i0];
    Ar[i0] = ar_ + tr; Ai[i0] = ai_ + ti;
    Ar[i1] = ar_ - tr; Ai[i1] = ai_ - ti;
    Stage4<M + 1>::run(Ar, Ai);
  }
};
template<> struct Stage4<32>{ static DEV void run(float*, float*){} };

// ---------------- real-split + magnitude + mel scatter on explicit values ----------------
template<int K>
DEV void do_pair_v(float P, float Q, float R, float S, float* mel){
  float zer = P + R, zei = Q - S;
  float zor = Q + S, zoi = R - P;
  constexpr float c = (float)ccos(kPI * (double)K / 64.0);
  constexpr float s = (float)csin(kPI * (double)K / 64.0);
  float A  = fmaf(c, zor,  s * zoi);
  float Bv = fmaf(c, zoi, -(s * zor));
  scatter<K>(mel, magf(zer + A, zei + Bv));
  if constexpr (bin_used(64 - K)){
    scatter<64 - K>(mel, magf(zer - A, Bv - zei));
  }
}

// ---------------- fused stage-5 + real-split (R7-proven) ----------------
template<int R> struct Final {
  static DEV void run(float* Ar, float* Ai, float* mel){
    constexpr float c = (float)ccos(kPI * (double)R / 32.0);
    constexpr float s = (float)csin(kPI * (double)R / 32.0);
    float ar = Ar[R], ai = Ai[R], br = Ar[R+32], bi = Ai[R+32];
    float tr = fmaf(c, br,  s * bi);
    float ti = fmaf(c, bi, -(s * br));
    float zRr  = ar + tr, zRi  = ai + ti;          // Z[R]
    float zRpr = ar - tr, zRpi = ai - ti;          // Z[R+32]
    float a2r = Ar[32-R], a2i = Ai[32-R], b2r = Ar[64-R], b2i = Ai[64-R];
    float t2r = fmaf(-c, b2r,  s * b2i);
    float t2i = fmaf(-c, b2i, -(s * b2r));
    float zSr  = a2r + t2r, zSi  = a2i + t2i;      // Z[32-R]
    float zSpr = a2r - t2r, zSpi = a2i - t2i;      // Z[64-R]
    do_pair_v<R>     (zRr, zRi, zSpr, zSpi, mel);  // pair R: Z[R], Z[64-R]
    do_pair_v<32 - R>(zSr, zSi, zRpr, zRpi, mel);  // pair 32-R: Z[32-R], Z[32+R]
    Final<R + 1>::run(Ar, Ai, mel);
  }
};
template<> struct Final<16> {
  static DEV void run(float* Ar, float* Ai, float* mel){
    float ar = Ar[16], ai = Ai[16], br = Ar[48], bi = Ai[48];
    do_pair_v<16>(ar + bi, ai - br, ar - bi, ai + br, mel);   // w = -i
  }
};

// ---------------- store mel row to SMEM (untouched bins -> literal 0) ----------------
template<int J> struct StoreLoop {
  static DEV void run(float* dst, const float* mel){
    if constexpr (mel_used(J)) dst[J] = mel[J];
    else dst[J] = 0.0f;
    StoreLoop<J + 1>::run(dst, mel);
  }
};
template<> struct StoreLoop<80>{ static DEV void run(float*, const float*){} };

// ---------------- kernel ----------------
static constexpr int TPB = 128;       // one thread = one frame
static constexpr int NCOL = 81;       // 1 raw sample + 80 mel

__global__ void __launch_bounds__(TPB, 4)
mel_kernel(const float* __restrict__ x, float* __restrict__ out){
  __shared__ __align__(8) float sxe[256];         // x[t0 + i]
  __shared__ __align__(8) float sxo[256];         // x[t0 + 1 + i]  (shifted copy)
  __shared__ __align__(16) float sout[TPB * NCOL];

  const int tid = threadIdx.x;
  const int t0  = blockIdx.x * TPB;
  const float* xrow = x + (size_t)blockIdx.y * 16384;

  #pragma unroll
  for (int i = tid; i < 256; i += TPB){
    int t = t0 + i;
    sxe[i] = (t < 16384) ? xrow[t] : 0.0f;
    int t2 = t + 1;
    sxo[i] = (t2 < 16384) ? xrow[t2] : 0.0f;
  }
  __syncthreads();

  // Aligned float2 base: bp2[s] = (x[t0+tid+2s], x[t0+tid+2s+1]) for either tid parity.
  const float2* bp2 = (tid & 1) ? (const float2*)(sxo + (tid - 1))
                                : (const float2*)(sxe + tid);

  float Ar[64], Ai[64], mel[80];
  Fused0<0>::run(Ar, Ai, bp2);                    // window + bitrev load (LDS.64) + stage 0
  Stage1<0>::run(Ar, Ai);                         // stage 1 (trivial twiddles)
  R4Loop<2, 0>::run(Ar, Ai);                      // stages 2+3 fused radix-4
  Stage4<0>::run(Ar, Ai);                         // stage 4 radix-2
  // r = 0 of stage 5: Z[32] = pos0 - pos32 (w = 1); bin 0 excluded by mel matrix.
  scatter<32>(mel, magf(Ar[0] - Ar[32], Ai[0] - Ai[32]));
  Final<1>::run(Ar, Ai, mel);                     // fused stage-5 + realsplit + mag + mel

  // stage 81-float output row in SMEM (stride 81 -> bank-conflict-free)
  float* row = sout + tid * NCOL;
  row[0] = sxe[tid];
  StoreLoop<0>::run(row + 1, mel);
  __syncthreads();

  // Bulk async 1D store SMEM -> GMEM (contiguous 41472 B, 16B-aligned both sides).
  if (tid == 0){
    uint32_t sa;
    asm("{ .reg .u64 t; cvta.to.shared.u64 t, %1; cvt.u32.u64 %0, t; }"
        : "=r"(sa) : "l"(sout));
    float* gdst = out + ((size_t)blockIdx.y * 16384 + (size_t)t0) * NCOL;
    asm volatile("fence.proxy.async.shared::cta;" ::: "memory");
    asm volatile("cp.async.bulk.global.shared::cta.bulk_group [%0], [%1], %2;"
                 :: "l"(gdst), "r"(sa), "r"((uint32_t)(TPB * NCOL * 4)) : "memory");
    asm volatile("cp.async.bulk.commit_group;" ::: "memory");
    asm volatile("cp.async.bulk.wait_group 0;" ::: "memory");
  }
}

extern "C" void kernel_launch(void* const* d_in, const int* in_sizes, int n_in,
                              void* d_out, int out_size){
  (void)in_sizes; (void)n_in; (void)out_size;
  const float* x = (const float*)d_in[0];
  float* out = (float*)d_out;
  dim3 grid(16384 / TPB, 16);
  mel_kernel<<<grid, TPB>>>(x, out);
}